// round 1
// baseline (speedup 1.0000x reference)
#include <cuda_runtime.h>
#include <math.h>

// ---------------- problem constants ----------------
#define SEQ   1024
#define HDIM  2048
#define NH    16
#define KVH   8
#define HD    128
#define QKH   24          // NH + KVH
#define QKVO  4096        // (QKH+KVH)*HD
#define DFF   6144
#define VOC   32000
#define NLAY  2

// ---------------- scratch (device globals; no allocs allowed) ----------------
__device__ float g_x    [SEQ * HDIM];
__device__ float g_hn   [SEQ * HDIM];
__device__ float g_qkv  [SEQ * QKVO];
__device__ float g_q    [NH  * SEQ * HD];
__device__ float g_k    [KVH * SEQ * HD];
__device__ float g_vt   [KVH * HD * SEQ];     // V transposed: [kvh][d][s]
__device__ float g_sc   [NH * SEQ * SEQ];     // attention scores / probs
__device__ float g_ao   [SEQ * HDIM];         // attention output (S, NH*HD)
__device__ float g_gu   [SEQ * 2 * DFF];
__device__ float g_act  [SEQ * DFF];
__device__ float g_last [HDIM];

// ---------------- generic NT SGEMM: C[z] = A[z](MxK) * B[z>>shift](NxK)^T (+resid) ----
// Tiles: 128x128x16, 256 threads, 8x8 per thread. All M,N multiples of 128, K of 16.
__global__ __launch_bounds__(256) void sgemm_nt(
    const float* __restrict__ A, int lda,
    const float* __restrict__ B, int ldb,
    float* __restrict__ C, int ldc,
    int K,
    const float* __restrict__ resid, int ldr,
    long long bsA, long long bsB, long long bsC, int bShiftB)
{
    const long long z = blockIdx.z;
    A += z * bsA;
    B += (z >> bShiftB) * bsB;
    C += z * bsC;

    __shared__ __align__(16) float As[16][132];
    __shared__ __align__(16) float Bs[16][132];

    const int m0 = blockIdx.y * 128;
    const int n0 = blockIdx.x * 128;
    const int tid = threadIdx.x;
    const int ty = tid >> 4;      // 0..15
    const int tx = tid & 15;      // 0..15

    float acc[8][8];
#pragma unroll
    for (int i = 0; i < 8; i++)
#pragma unroll
        for (int j = 0; j < 8; j++) acc[i][j] = 0.f;

    for (int k0 = 0; k0 < K; k0 += 16) {
#pragma unroll
        for (int it = 0; it < 2; it++) {
            int v   = tid + it * 256;      // 0..511
            int row = v >> 2;              // 0..127
            int kq  = (v & 3) << 2;        // 0,4,8,12
            float4 av = *(const float4*)(A + (long long)(m0 + row) * lda + k0 + kq);
            As[kq + 0][row] = av.x; As[kq + 1][row] = av.y;
            As[kq + 2][row] = av.z; As[kq + 3][row] = av.w;
            float4 bv = *(const float4*)(B + (long long)(n0 + row) * ldb + k0 + kq);
            Bs[kq + 0][row] = bv.x; Bs[kq + 1][row] = bv.y;
            Bs[kq + 2][row] = bv.z; Bs[kq + 3][row] = bv.w;
        }
        __syncthreads();

#pragma unroll
        for (int kk = 0; kk < 16; kk++) {
            float4 a0 = *(const float4*)(&As[kk][ty * 8]);
            float4 a1 = *(const float4*)(&As[kk][ty * 8 + 4]);
            float4 b0 = *(const float4*)(&Bs[kk][tx * 8]);
            float4 b1 = *(const float4*)(&Bs[kk][tx * 8 + 4]);
            float a[8] = {a0.x, a0.y, a0.z, a0.w, a1.x, a1.y, a1.z, a1.w};
            float b[8] = {b0.x, b0.y, b0.z, b0.w, b1.x, b1.y, b1.z, b1.w};
#pragma unroll
            for (int i = 0; i < 8; i++)
#pragma unroll
                for (int j = 0; j < 8; j++)
                    acc[i][j] += a[i] * b[j];
        }
        __syncthreads();
    }

#pragma unroll
    for (int i = 0; i < 8; i++) {
        int m = m0 + ty * 8 + i;
#pragma unroll
        for (int j = 0; j < 8; j++) {
            int n = n0 + tx * 8 + j;
            float val = acc[i][j];
            if (resid) val += resid[(long long)m * ldr + n];
            C[(long long)m * ldc + n] = val;
        }
    }
}

// ---------------- row-wise l2norm: out = in * rsqrt(sum(in^2)) ----------------
__global__ void l2norm_rows(const float* __restrict__ in, float* __restrict__ out, int cols)
{
    const int row = blockIdx.x;
    const float* x = in + (long long)row * cols;
    float* y = out + (long long)row * cols;
    float s = 0.f;
    for (int c = threadIdx.x; c < cols; c += blockDim.x) { float v = x[c]; s += v * v; }
    __shared__ float red[32];
#pragma unroll
    for (int o = 16; o; o >>= 1) s += __shfl_xor_sync(0xffffffffu, s, o);
    if ((threadIdx.x & 31) == 0) red[threadIdx.x >> 5] = s;
    __syncthreads();
    const int nw = blockDim.x >> 5;
    if (threadIdx.x < 32) {
        float t = (threadIdx.x < nw) ? red[threadIdx.x] : 0.f;
#pragma unroll
        for (int o = 16; o; o >>= 1) t += __shfl_xor_sync(0xffffffffu, t, o);
        if (threadIdx.x == 0) red[0] = rsqrtf(t);
    }
    __syncthreads();
    const float r = red[0];
    for (int c = threadIdx.x; c < cols; c += blockDim.x) y[c] = x[c] * r;
}

// ---------------- per-head l2norm * qk_norm_w, then RoPE; scatter into Q/K ----------------
// grid: (SEQ, QKH), block: 128 (one thread per dim)
__global__ void qk_rope(const float* __restrict__ qkv, const float* __restrict__ qknw,
                        const float* __restrict__ cosb, const float* __restrict__ sinb,
                        float* __restrict__ Q, float* __restrict__ Kb)
{
    const int s = blockIdx.x;
    const int h = blockIdx.y;      // 0..23
    const int d = threadIdx.x;     // 0..127
    __shared__ float sv[128];
    __shared__ float red[4];

    float v = qkv[(long long)s * QKVO + h * HD + d];
    float ss = v * v;
#pragma unroll
    for (int o = 16; o; o >>= 1) ss += __shfl_xor_sync(0xffffffffu, ss, o);
    if ((d & 31) == 0) red[d >> 5] = ss;
    __syncthreads();
    const float tot = red[0] + red[1] + red[2] + red[3];
    const float nv = v * rsqrtf(tot) * qknw[h * HD + d];
    sv[d] = nv;
    __syncthreads();
    const float rot = (d < 64) ? sv[d + 64] : sv[d - 64];
    const float ov = nv * cosb[s * HD + d] + rot * sinb[s * HD + d];
    if (h < NH) Q[((long long)h * SEQ + s) * HD + d] = ov;
    else        Kb[((long long)(h - NH) * SEQ + s) * HD + d] = ov;
}

// ---------------- V transpose: qkv[s][3072 + h*128 + d] -> Vt[h][d][s] ----------------
__global__ void v_transpose(const float* __restrict__ qkv, float* __restrict__ Vt)
{
    __shared__ float t[32][33];
    const int h = blockIdx.z;
    const int s0 = blockIdx.x * 32;
    const int d0 = blockIdx.y * 32;
    const int s = s0 + threadIdx.y;
    const int d = d0 + threadIdx.x;
    t[threadIdx.y][threadIdx.x] = qkv[(long long)s * QKVO + QKH * HD + h * HD + d];
    __syncthreads();
    Vt[((long long)h * HD + d0 + threadIdx.y) * SEQ + s0 + threadIdx.x] = t[threadIdx.x][threadIdx.y];
}

// ---------------- causal softmax with additive -128*mask penalty ----------------
// grid: (SEQ, NH), block: 256; row length SEQ (4 per thread)
__global__ void softmax_causal(float* __restrict__ scores, const float* __restrict__ maskp)
{
    const int q = blockIdx.x;
    const int h = blockIdx.y;
    float* row = scores + ((long long)h * SEQ + q) * SEQ;
    const float mpen = -128.f * maskp[0];
    const int tid = threadIdx.x;

    float vals[4];
    float mx = -1e30f;
#pragma unroll
    for (int i = 0; i < 4; i++) {
        int k = tid + i * 256;
        float v = row[k] + (k > q ? mpen : 0.f);
        vals[i] = v;
        mx = fmaxf(mx, v);
    }
    __shared__ float redm[8];
    __shared__ float reds[8];
#pragma unroll
    for (int o = 16; o; o >>= 1) mx = fmaxf(mx, __shfl_xor_sync(0xffffffffu, mx, o));
    if ((tid & 31) == 0) redm[tid >> 5] = mx;
    __syncthreads();
    if (tid < 32) {
        float m2 = (tid < 8) ? redm[tid] : -1e30f;
#pragma unroll
        for (int o = 16; o; o >>= 1) m2 = fmaxf(m2, __shfl_xor_sync(0xffffffffu, m2, o));
        if (tid == 0) redm[0] = m2;
    }
    __syncthreads();
    mx = redm[0];

    float s = 0.f;
#pragma unroll
    for (int i = 0; i < 4; i++) { vals[i] = expf(vals[i] - mx); s += vals[i]; }
#pragma unroll
    for (int o = 16; o; o >>= 1) s += __shfl_xor_sync(0xffffffffu, s, o);
    if ((tid & 31) == 0) reds[tid >> 5] = s;
    __syncthreads();
    if (tid < 32) {
        float t2 = (tid < 8) ? reds[tid] : 0.f;
#pragma unroll
        for (int o = 16; o; o >>= 1) t2 += __shfl_xor_sync(0xffffffffu, t2, o);
        if (tid == 0) reds[0] = 1.f / t2;
    }
    __syncthreads();
    const float inv = reds[0];
#pragma unroll
    for (int i = 0; i < 4; i++) row[tid + i * 256] = vals[i] * inv;
}

// ---------------- SwiGLU: act = silu(gate) * up ----------------
__global__ void silu_mul(const float* __restrict__ gu, float* __restrict__ act)
{
    const long long i = (long long)blockIdx.x * blockDim.x + threadIdx.x;
    const int s = (int)(i / DFF);
    const int f = (int)(i % DFF);
    const float g = gu[(long long)s * (2 * DFF) + f];
    const float u = gu[(long long)s * (2 * DFF) + DFF + f];
    act[i] = (g / (1.f + expf(-g))) * u;
}

// ---------------- lm_head GEMV: out[v] = sum_h last[h]*W[v][h]; 1 warp / output ----------------
__global__ void lm_head(const float* __restrict__ last, const float* __restrict__ W,
                        float* __restrict__ out)
{
    const int warp = threadIdx.x >> 5;
    const int lane = threadIdx.x & 31;
    const int v = blockIdx.x * 8 + warp;
    const float* w = W + (long long)v * HDIM;
    float s = 0.f;
#pragma unroll
    for (int j = lane * 4; j < HDIM; j += 128) {
        float4 wv = *(const float4*)(w + j);
        float4 lv = *(const float4*)(last + j);
        s += wv.x * lv.x + wv.y * lv.y + wv.z * lv.z + wv.w * lv.w;
    }
#pragma unroll
    for (int o = 16; o; o >>= 1) s += __shfl_xor_sync(0xffffffffu, s, o);
    if (lane == 0) out[v] = s;
}

// ---------------- launcher ----------------
extern "C" void kernel_launch(void* const* d_in, const int* in_sizes, int n_in,
                              void* d_out, int out_size)
{
    const float* hidden = (const float*)d_in[0];
    const float* qkv_w  = (const float*)d_in[1];
    const float* qknw   = (const float*)d_in[2];
    const float* o_w    = (const float*)d_in[3];
    const float* gu_w   = (const float*)d_in[4];
    const float* dn_w   = (const float*)d_in[5];
    const float* lm_w   = (const float*)d_in[6];
    const float* cosb   = (const float*)d_in[7];
    const float* sinb   = (const float*)d_in[8];
    const float* maskp  = (const float*)d_in[9];
    float* outp = (float*)d_out;

    float *px, *phn, *pqkv, *pq, *pk, *pvt, *psc, *pao, *pgu, *pact, *plast;
    cudaGetSymbolAddress((void**)&px,    g_x);
    cudaGetSymbolAddress((void**)&phn,   g_hn);
    cudaGetSymbolAddress((void**)&pqkv,  g_qkv);
    cudaGetSymbolAddress((void**)&pq,    g_q);
    cudaGetSymbolAddress((void**)&pk,    g_k);
    cudaGetSymbolAddress((void**)&pvt,   g_vt);
    cudaGetSymbolAddress((void**)&psc,   g_sc);
    cudaGetSymbolAddress((void**)&pao,   g_ao);
    cudaGetSymbolAddress((void**)&pgu,   g_gu);
    cudaGetSymbolAddress((void**)&pact,  g_act);
    cudaGetSymbolAddress((void**)&plast, g_last);

    const float* xin = hidden;   // residual source for layer 0 attention block

    for (int l = 0; l < NLAY; l++) {
        // pre-attn l2norm
        l2norm_rows<<<SEQ, 256>>>(xin, phn, HDIM);

        // QKV projection: (S,H) x (4096,H)^T
        sgemm_nt<<<dim3(QKVO / 128, SEQ / 128, 1), 256>>>(
            phn, HDIM, qkv_w + (long long)l * QKVO * HDIM, HDIM,
            pqkv, QKVO, HDIM, nullptr, 0, 0, 0, 0, 0);

        // per-head norm + RoPE, V transpose
        qk_rope<<<dim3(SEQ, QKH), 128>>>(pqkv, qknw + (long long)l * QKH * HD, cosb, sinb, pq, pk);
        v_transpose<<<dim3(SEQ / 32, HD / 32, KVH), dim3(32, 32)>>>(pqkv, pvt);

        // scores[h] = Q[h] (S,HD) x K[h/2] (S,HD)^T
        sgemm_nt<<<dim3(SEQ / 128, SEQ / 128, NH), 256>>>(
            pq, HD, pk, HD, psc, SEQ, HD, nullptr, 0,
            (long long)SEQ * HD, (long long)SEQ * HD, (long long)SEQ * SEQ, 1);

        softmax_causal<<<dim3(SEQ, NH), 256>>>(psc, maskp);

        // out[h] = P[h] (S,S) x Vt[h/2] (HD,S)^T  -> pao[:, h*128:(h+1)*128]
        sgemm_nt<<<dim3(HD / 128, SEQ / 128, NH), 256>>>(
            psc, SEQ, pvt, SEQ, pao, HDIM, SEQ, nullptr, 0,
            (long long)SEQ * SEQ, (long long)HD * SEQ, (long long)HD, 1);

        // O projection + residual: x = resid + ao x o_w^T
        sgemm_nt<<<dim3(HDIM / 128, SEQ / 128, 1), 256>>>(
            pao, HDIM, o_w + (long long)l * HDIM * HDIM, HDIM,
            px, HDIM, HDIM, xin, HDIM, 0, 0, 0, 0);

        // MLP
        l2norm_rows<<<SEQ, 256>>>(px, phn, HDIM);
        sgemm_nt<<<dim3(2 * DFF / 128, SEQ / 128, 1), 256>>>(
            phn, HDIM, gu_w + (long long)l * 2 * DFF * HDIM, HDIM,
            pgu, 2 * DFF, HDIM, nullptr, 0, 0, 0, 0, 0);
        silu_mul<<<(SEQ * DFF) / 256, 256>>>(pgu, pact);
        sgemm_nt<<<dim3(HDIM / 128, SEQ / 128, 1), 256>>>(
            pact, DFF, dn_w + (long long)l * HDIM * DFF, DFF,
            px, HDIM, DFF, px, HDIM, 0, 0, 0, 0);

        xin = px;
    }

    // final: l2norm last token, lm_head
    l2norm_rows<<<1, 256>>>(px + (long long)(SEQ - 1) * HDIM, plast, HDIM);
    lm_head<<<VOC / 8, 256>>>(plast, lm_w, outp);
}